// round 16
// baseline (speedup 1.0000x reference)
#include <cuda_runtime.h>
#include <cuda_fp16.h>
#include <math.h>
#include <stdint.h>

#define NB    8
#define CCH   640
#define HW    1024
#define NH    8
#define DH    80
#define DCTX  512
#define GRP   32
#define CPG   20
#define SKCTX 77

// ---------------- fp32 scratch ----------------
__device__ float  g_xseq [NB*HW*CCH];
__device__ float  g_gnstat[NB*GRP*2];
__device__ float  g_lin1bi[8*CCH];
// ---------------- fp16 scratch ----------------
__device__ __half h_gn  [NB*HW*CCH];
__device__ __half h_t   [NB*HW*CCH];
__device__ __half h_attn[NB*HW*CCH];
__device__ __half h_ctx [NB*SKCTX*DCTX];
__device__ __half h_kv  [NB*SKCTX*2*CCH];
__device__ __half h_ffg [NB*HW*4*CCH];
__device__ __half h_x   [NB*HW*CCH];
__device__ __half h_qkv [NB*HW*3*CCH];
__device__ __half h_vt  [NB*CCH*HW];
__device__ __half h_w   [8847360];       // all weights, fp16, [N,K]

// ---------------- GroupNorm stats ----------------
__global__ __launch_bounds__(1024)
void gn_stats(const float* __restrict__ x) {
    int ng = blockIdx.x;
    int n = ng / GRP, g = ng % GRP;
    const float4* base = (const float4*)(x + ((size_t)n*CCH + (size_t)g*CPG) * HW);
    float s = 0.f, s2 = 0.f;
    for (int i = threadIdx.x; i < CPG*HW/4; i += 1024) {
        float4 v = base[i];
        s  += v.x + v.y + v.z + v.w;
        s2 += v.x*v.x + v.y*v.y + v.z*v.z + v.w*v.w;
    }
    __shared__ float rs[1024], rq[1024];
    rs[threadIdx.x] = s; rq[threadIdx.x] = s2;
    __syncthreads();
    for (int o = 512; o > 0; o >>= 1) {
        if (threadIdx.x < o) { rs[threadIdx.x] += rs[threadIdx.x+o]; rq[threadIdx.x] += rq[threadIdx.x+o]; }
        __syncthreads();
    }
    if (threadIdx.x == 0) {
        float inv_n = 1.f / (float)(CPG*HW);
        float mu  = rs[0] * inv_n;
        float var = rq[0] * inv_n - mu*mu;
        g_gnstat[ng*2]   = mu;
        g_gnstat[ng*2+1] = rsqrtf(var + 1e-6f);
    }
}

// ---------------- GroupNorm apply + transpose -> fp16 [n,p,c] ----------------
__global__ void gn_apply(const float* __restrict__ x,
                         const float* __restrict__ s, const float* __restrict__ b) {
    __shared__ float tile[32][33];
    int n = blockIdx.z;
    int p0 = blockIdx.x*32, c0 = blockIdx.y*32;
    int tx = threadIdx.x, ty = threadIdx.y;
    #pragma unroll
    for (int i = 0; i < 4; i++) {
        int c = c0 + ty + i*8;
        int ng = n*GRP + c / CPG;
        float mu = g_gnstat[ng*2], is = g_gnstat[ng*2+1];
        float v = x[((size_t)n*CCH + c)*HW + p0 + tx];
        tile[ty + i*8][tx] = (v - mu) * is * s[c] + b[c];
    }
    __syncthreads();
    #pragma unroll
    for (int i = 0; i < 4; i++) {
        int p = p0 + ty + i*8;
        h_gn[((size_t)n*HW + p)*CCH + c0 + tx] = __float2half(tile[tx][ty + i*8]);
    }
}

// ---------------- merged weight transpose+convert ----------------
struct WSeg { const float* src; __half* dst; int K, N, tilesX, tileOff, ileave; };
struct W8 { WSeg w[8]; };
__global__ void wtrans_all(W8 ws) {
    __shared__ float t[32][33];
    int bid = blockIdx.x;
    int si = 0;
    #pragma unroll
    for (int i = 1; i < 8; i++)
        if (bid >= ws.w[i].tileOff) si = i;
    WSeg sg = ws.w[si];
    int local = bid - sg.tileOff;
    int n0 = (local % sg.tilesX) * 32;
    int k0 = (local / sg.tilesX) * 32;
    int tx = threadIdx.x, ty = threadIdx.y;
    #pragma unroll
    for (int i = 0; i < 4; i++)
        t[ty + i*8][tx] = sg.src[(size_t)(k0 + ty + i*8)*sg.N + n0 + tx];
    __syncthreads();
    int half = sg.N >> 1;
    #pragma unroll
    for (int i = 0; i < 4; i++) {
        int r = n0 + ty + i*8;
        int rr = sg.ileave ? ((r < half) ? 2*r : 2*(r - half) + 1) : r;
        sg.dst[(size_t)rr*sg.K + k0 + tx] = __float2half(t[tx][ty + i*8]);
    }
}

// ---------------- merged converts + lin1 bias interleave ----------------
__global__ void cvt_all(const float* s0, __half* d0, int e0,
                        const float* s1, __half* d1, int e1,
                        const float* s2, __half* d2, int e2,
                        const float* b,  float* bi,  int e3) {
    int i = blockIdx.x * 256 + threadIdx.x;
    if (i >= e0 + e1 + e2) {
        int off = i - e0 - e1 - e2;
        if (off < e3) {
            int j = off * 4;
            float4 a = *(const float4*)(b + j);
            float4 g = *(const float4*)(b + j + 4*CCH);
            *(float4*)(bi + 2*j)     = make_float4(a.x, g.x, a.y, g.y);
            *(float4*)(bi + 2*j + 4) = make_float4(a.z, g.z, a.w, g.w);
        }
        return;
    }
    const float* s; __half* d; int off;
    if (i < e0) { s = s0; d = d0; off = i; }
    else if (i < e0 + e1) { s = s1; d = d1; off = i - e0; }
    else { s = s2; d = d2; off = i - e0 - e1; }
    float4 v = ((const float4*)s)[off];
    union { uint2 u; __half2 h[2]; } pk;
    pk.h[0] = __floats2half2_rn(v.x, v.y);
    pk.h[1] = __floats2half2_rn(v.z, v.w);
    ((uint2*)d)[off] = pk.u;
}

// ---------------- LayerNorm fp32 in -> fp16 out ----------------
__global__ __launch_bounds__(160)
void layernorm(const float* __restrict__ in,
               const float* __restrict__ s, const float* __restrict__ b,
               __half* __restrict__ out) {
    int row = blockIdx.x;
    int tid = threadIdx.x;
    const float4* r4 = (const float4*)(in + (size_t)row * CCH);
    float4 v = r4[tid];
    float sum = v.x + v.y + v.z + v.w;
    float sq  = v.x*v.x + v.y*v.y + v.z*v.z + v.w*v.w;
    #pragma unroll
    for (int o = 16; o > 0; o >>= 1) {
        sum += __shfl_xor_sync(~0u, sum, o);
        sq  += __shfl_xor_sync(~0u, sq,  o);
    }
    __shared__ float ws[5], wq[5];
    int w = tid >> 5;
    if ((tid & 31) == 0) { ws[w] = sum; wq[w] = sq; }
    __syncthreads();
    sum = ws[0] + ws[1] + ws[2] + ws[3] + ws[4];
    sq  = wq[0] + wq[1] + wq[2] + wq[3] + wq[4];
    float mu  = sum / (float)CCH;
    float inv = rsqrtf(sq / (float)CCH - mu*mu + 1e-5f);
    float4 sc = ((const float4*)s)[tid];
    float4 bb = ((const float4*)b)[tid];
    union { uint2 u; __half2 h[2]; } pk;
    pk.h[0] = __floats2half2_rn((v.x - mu) * inv * sc.x + bb.x, (v.y - mu) * inv * sc.y + bb.y);
    pk.h[1] = __floats2half2_rn((v.z - mu) * inv * sc.z + bb.z, (v.w - mu) * inv * sc.w + bb.w);
    ((uint2*)(out + (size_t)row * CCH))[tid] = pk.u;
}

// ---------------- mma / cp.async helpers ----------------
__device__ __forceinline__ void mma16h(float c[4], uint32_t a0, uint32_t a1, uint32_t a2, uint32_t a3,
                                       uint32_t b0, uint32_t b1) {
    asm volatile("mma.sync.aligned.m16n8k16.row.col.f32.f16.f16.f32 "
        "{%0,%1,%2,%3}, {%4,%5,%6,%7}, {%8,%9}, {%0,%1,%2,%3};"
        : "+f"(c[0]), "+f"(c[1]), "+f"(c[2]), "+f"(c[3])
        : "r"(a0), "r"(a1), "r"(a2), "r"(a3), "r"(b0), "r"(b1));
}
__device__ __forceinline__ void ldsm4(uint32_t r[4], uint32_t addr) {
    asm volatile("ldmatrix.sync.aligned.m8n8.x4.shared.b16 {%0,%1,%2,%3}, [%4];"
        : "=r"(r[0]), "=r"(r[1]), "=r"(r[2]), "=r"(r[3]) : "r"(addr));
}
__device__ __forceinline__ void cpa16(void* dst, const void* src, bool valid) {
    uint32_t d = (uint32_t)__cvta_generic_to_shared(dst);
    int sz = valid ? 16 : 0;
    asm volatile("cp.async.cg.shared.global [%0], [%1], 16, %2;" :: "r"(d), "l"(src), "r"(sz));
}
#define CP_COMMIT() asm volatile("cp.async.commit_group;")
#define CP_WAIT1()  asm volatile("cp.async.wait_group 1;")
__device__ __forceinline__ uint32_t hpack(float a, float b) {
    __half2 h = __floats2half2_rn(a, b);
    return *(uint32_t*)&h;
}

// ---------------- fp16 GEMM core: MBx128x64 tiles, 3-stage cp.async, all-ldmatrix ----------------
// MODE 0: normal  MODE 1: geglu epilogue  MODE 2: NCHW transpose+residual
// MODE 3: fp16 out + transposed V side-store  (MODE 1/2/3 require MB=128)
#define RS36 36
#define NST  3
#define SMEM_FOR(MB) (NST*((MB)+128)*RS36*4)
template<int MODE, int MB>
__device__ __forceinline__
void gemm_core(uint32_t* sm, int bm, int bn,
               const __half* __restrict__ A, int lda,
               const __half* __restrict__ B,
               const float* __restrict__ bias,
               const float* __restrict__ res,
               float* __restrict__ C, __half* __restrict__ Ch, int ldc,
               int M, int N, int K) {
    constexpr int NMI  = MB / 32;          // m-fragments per warp
    constexpr int BUFA = MB * RS36;
    constexpr int BUFB = 128 * RS36;
    uint32_t* As = sm;
    uint32_t* Bs = sm + NST*BUFA;
    uint32_t a_u32 = (uint32_t)__cvta_generic_to_shared(As);
    uint32_t b_u32 = (uint32_t)__cvta_generic_to_shared(Bs);

    int tid = threadIdx.x;
    int lane = tid & 31, warp = tid >> 5;
    int gr = lane >> 2, t4 = lane & 3;
    int wm = (warp >> 2) * (MB/2), wn = (warp & 3) * 32;

    uint32_t lds_off  = (uint32_t)((lane & 15) * (RS36*4) + ((lane >> 4) << 4));
    uint32_t ldsb_off = (uint32_t)(((lane & 7) + ((lane >> 4) << 3)) * (RS36*4)
                                   + (((lane >> 3) & 1) << 4));

    auto stage = [&](int kt, int buf) {
        #pragma unroll
        for (int i = 0; i < MB/32; i++) {
            int c = tid + i*256;
            int row = c >> 3, seg = c & 7;
            int gm = bm + row;
            cpa16(As + buf*BUFA + row*RS36 + seg*4,
                  A + ((size_t)(gm < M ? gm : 0))*lda + kt*64 + seg*8, gm < M);
        }
        #pragma unroll
        for (int i = 0; i < 4; i++) {
            int c = tid + i*256;
            int row = c >> 3, seg = c & 7;
            int gn = bn + row;
            cpa16(Bs + buf*BUFB + row*RS36 + seg*4,
                  B + ((size_t)(gn < N ? gn : 0))*K + kt*64 + seg*8, gn < N);
        }
    };

    float acc[NMI][4][4];
    #pragma unroll
    for (int i = 0; i < NMI; i++)
        #pragma unroll
        for (int j = 0; j < 4; j++)
            #pragma unroll
            for (int r = 0; r < 4; r++) acc[i][j][r] = 0.f;

    int nk = K >> 6;
    stage(0, 0); CP_COMMIT();
    stage(1, 1); CP_COMMIT();

    int buf = 0;
    for (int t = 0; t < nk; t++) {
        CP_WAIT1();
        __syncthreads();
        if (t + 2 < nk) stage(t+2, (t+2) % NST);
        CP_COMMIT();

        uint32_t a_base = a_u32 + buf*(BUFA*4) + lds_off;
        uint32_t b_base = b_u32 + buf*(BUFB*4) + ldsb_off;

        #pragma unroll
        for (int ks = 0; ks < 4; ks++) {
            uint32_t af[NMI][4], bf[4][2];
            #pragma unroll
            for (int mi = 0; mi < NMI; mi++)
                ldsm4(af[mi], a_base + (uint32_t)((wm + mi*16)*(RS36*4) + ks*32));
            #pragma unroll
            for (int p = 0; p < 2; p++) {
                uint32_t r[4];
                ldsm4(r, b_base + (uint32_t)((wn + p*16)*(RS36*4) + ks*32));
                bf[2*p][0]   = r[0]; bf[2*p][1]   = r[1];
                bf[2*p+1][0] = r[2]; bf[2*p+1][1] = r[3];
            }
            #pragma unroll
            for (int mi = 0; mi < NMI; mi++)
                #pragma unroll
                for (int ni = 0; ni < 4; ni++)
                    mma16h(acc[mi][ni], af[mi][0], af[mi][1], af[mi][2], af[mi][3],
                           bf[ni][0], bf[ni][1]);
        }
        buf = (buf + 1 == NST) ? 0 : buf + 1;
    }

    if (MODE == 2) {
        __syncthreads();
        float* eb = (float*)sm;          // [128 cols][132]
        #pragma unroll
        for (int mi = 0; mi < NMI; mi++) {
            #pragma unroll
            for (int ni = 0; ni < 4; ni++) {
                int col_l = wn + ni*8 + t4*2;
                int col0  = bn + col_l;
                #pragma unroll
                for (int half_r = 0; half_r < 2; half_r++) {
                    int row_l = wm + mi*16 + gr + half_r*8;
                    eb[(col_l)*132 + row_l]   = acc[mi][ni][half_r*2 + 0] + bias[col0];
                    eb[(col_l+1)*132 + row_l] = acc[mi][ni][half_r*2 + 1] + bias[col0+1];
                }
            }
        }
        __syncthreads();
        int n = bm >> 10, p0 = bm & 1023;
        for (int i = tid; i < 128*32; i += 256) {
            int c = i >> 5, seg = i & 31;
            size_t off = ((size_t)(n*CCH + bn + c))*HW + p0 + seg*4;
            const float* e = eb + c*132 + seg*4;
            float4 xr = *(const float4*)(res + off);
            *(float4*)(C + off) = make_float4(e[0]+xr.x, e[1]+xr.y, e[2]+xr.z, e[3]+xr.w);
        }
        return;
    }

    if (MODE == 1) {
        __syncthreads();
        __half* eb = (__half*)sm;        // [128 rows][72]
        #pragma unroll
        for (int mi = 0; mi < NMI; mi++) {
            #pragma unroll
            for (int ni = 0; ni < 4; ni++) {
                int col_l = wn + ni*8 + t4*2;
                int col0  = bn + col_l;
                #pragma unroll
                for (int half_r = 0; half_r < 2; half_r++) {
                    int row_l = wm + mi*16 + gr + half_r*8;
                    float a = acc[mi][ni][half_r*2 + 0] + bias[col0];
                    float g = acc[mi][ni][half_r*2 + 1] + bias[col0+1];
                    float ge = 0.5f * g * (1.f + erff(g * 0.70710678118654752f));
                    eb[row_l*72 + (col_l >> 1)] = __float2half(a * ge);
                }
            }
        }
        __syncthreads();
        for (int i = tid; i < 128*8; i += 256) {
            int row = i >> 3, seg = i & 7;
            int grow = bm + row;
            if (grow < M)
                *(uint4*)(Ch + (size_t)grow*ldc + (bn >> 1) + seg*8) =
                    *(const uint4*)(eb + row*72 + seg*8);
        }
        return;
    }

    #pragma unroll
    for (int mi = 0; mi < NMI; mi++) {
        #pragma unroll
        for (int ni = 0; ni < 4; ni++) {
            int col0 = bn + wn + ni*8 + t4*2;
            #pragma unroll
            for (int half_r = 0; half_r < 2; half_r++) {
                int row = bm + wm + mi*16 + gr + half_r*8;
                if (row >= M) continue;
                float v0 = acc[mi][ni][half_r*2 + 0];
                float v1 = acc[mi][ni][half_r*2 + 1];
                if (bias) { v0 += bias[col0]; v1 += bias[col0+1]; }
                if (res) {
                    const float* rp = res + (size_t)row*ldc + col0;
                    v0 += rp[0]; v1 += rp[1];
                }
                if (MODE == 0 && C) *(float2*)(C + (size_t)row*ldc + col0) = make_float2(v0, v1);
                if (Ch) *(__half2*)(Ch + (size_t)row*ldc + col0) = __floats2half2_rn(v0, v1);
            }
        }
    }

    if (MODE == 3 && bn >= 2*CCH) {
        __syncthreads();
        __half* eb = (__half*)sm;        // [128][136]
        #pragma unroll
        for (int mi = 0; mi < NMI; mi++) {
            #pragma unroll
            for (int ni = 0; ni < 4; ni++) {
                int col_l = wn + ni*8 + t4*2;
                #pragma unroll
                for (int half_r = 0; half_r < 2; half_r++) {
                    int row_l = wm + mi*16 + gr + half_r*8;
                    eb[(col_l)*136 + row_l]   = __float2half(acc[mi][ni][half_r*2 + 0]);
                    eb[(col_l+1)*136 + row_l] = __float2half(acc[mi][ni][half_r*2 + 1]);
                }
            }
        }
        __syncthreads();
        __half* vt = (__half*)C;
        int b = bm >> 10, p0 = bm & 1023;
        int c0 = bn - 2*CCH;
        for (int i = tid; i < 128*16; i += 256) {
            int c = i >> 4, seg = i & 15;
            *(uint4*)(vt + ((size_t)(b*CCH + c0 + c))*HW + p0 + seg*8) =
                *(const uint4*)(eb + c*136 + seg*8);
        }
    }
}

template<int MODE, int MB>
__global__ __launch_bounds__(256, 2)
void gemm_h(const __half* __restrict__ A, int lda,
            const __half* __restrict__ B,
            const float* __restrict__ bias,
            const float* __restrict__ res,
            float* __restrict__ C, __half* __restrict__ Ch, int ldc,
            int M, int N, int K) {
    extern __shared__ uint32_t sm[];
    gemm_core<MODE, MB>(sm, blockIdx.y*MB, blockIdx.x*128,
                        A, lda, B, bias, res, C, Ch, ldc, M, N, K);
}

// dual GEMM (MB=64): CTAs [0,split) -> GEMM0, rest -> GEMM1
__global__ __launch_bounds__(256, 2)
void gemm_dual(const __half* A0, int lda0, const __half* B0, __half* Ch0, int ldc0,
               int M0, int N0, int K0, int nx0, int split,
               const __half* A1, int lda1, const __half* B1, __half* Ch1, int ldc1,
               int M1, int N1, int K1, int nx1) {
    extern __shared__ uint32_t sm[];
    int bid = blockIdx.x;
    if (bid < split) {
        gemm_core<0, 64>(sm, (bid/nx0)*64, (bid%nx0)*128,
                         A0, lda0, B0, nullptr, nullptr, nullptr, Ch0, ldc0, M0, N0, K0);
    } else {
        int l = bid - split;
        gemm_core<0, 64>(sm, (l/nx1)*64, (l%nx1)*128,
                         A1, lda1, B1, nullptr, nullptr, nullptr, Ch1, ldc1, M1, N1, K1);
    }
}

// ---------------- fused flash self-attention, full fp16 mma, 2 CTA/SM ----------------
#define KSR 88
#define VSR 72
__global__ __launch_bounds__(256, 2)
void flash_h(const __half* __restrict__ QKV, const __half* __restrict__ VT,
             __half* __restrict__ O) {
    constexpr int LD = 3*CCH;
    __shared__ __half Ks[2][64*KSR];
    __shared__ __half Vs[2][80*VSR];

    int tid = threadIdx.x, lane = tid & 31, w = tid >> 5;
    int z = blockIdx.y;
    int b = z >> 3, h = z & 7;
    int q0 = blockIdx.x * 128;
    int gr = lane >> 2, t4 = lane & 3;

    const __half* Kb  = QKV + ((size_t)b*HW)*LD + CCH + h*DH;
    const __half* Vtb = VT + ((size_t)b*CCH + h*DH)*HW;

    auto stage = [&](int kt, int buf) {
        #pragma unroll
        for (int i = 0; i < 3; i++) {
            int s = tid + i*256;
            if (s < 640) {
                int r = s / 10, g = s - r*10;
                cpa16(&Ks[buf][r*KSR + g*8], Kb + (size_t)(kt*64 + r)*LD + g*8, true);
            }
        }
        #pragma unroll
        for (int i = 0; i < 3; i++) {
            int s = tid + i*256;
            if (s < 640) {
                int r = s >> 3, g = s & 7;
                cpa16(&Vs[buf][r*VSR + g*8], Vtb + (size_t)r*HW + kt*64 + g*8, true);
            }
        }
    };

    stage(0, 0);
    CP_COMMIT();

    const __half2 qs2 = __float2half2_rn(0.1118033988749895f);
    uint32_t qf[5][4];
    {
        const __half* qp  = QKV + (size_t)(b*HW + q0 + w*16 + gr)*LD + h*DH;
        const __half* qp8 = qp + 8*LD;
        #pragma unroll
        for (int ks = 0; ks < 5; ks++) {
            __half2 v0 = __hmul2(*(const __half2*)(qp  + ks*16 + 2*t4),     qs2);
            __half2 v1 = __hmul2(*(const __half2*)(qp8 + ks*16 + 2*t4),     qs2);
            __half2 v2 = __hmul2(*(const __half2*)(qp  + ks*16 + 8 + 2*t4), qs2);
            __half2 v3 = __hmul2(*(const __half2*)(qp8 + ks*16 + 8 + 2*t4), qs2);
            qf[ks][0] = *(uint32_t*)&v0; qf[ks][1] = *(uint32_t*)&v1;
            qf[ks][2] = *(uint32_t*)&v2; qf[ks][3] = *(uint32_t*)&v3;
        }
    }

    float m0v = -1e30f, m1v = -1e30f, l0 = 0.f, l1 = 0.f;
    float oa[10][4];
    #pragma unroll
    for (int ni = 0; ni < 10; ni++) { oa[ni][0]=oa[ni][1]=oa[ni][2]=oa[ni][3]=0.f; }

    for (int kt = 0; kt < 16; kt++) {
        if (kt + 1 < 16) stage(kt+1, (kt+1) & 1);
        CP_COMMIT();
        CP_WAIT1();
        __syncthreads();
        const __half* Kc = Ks[kt & 1];
        const __half* Vc = Vs[kt & 1];

        float s[8][4];
        #pragma unroll
        for (int ni = 0; ni < 8; ni++) { s[ni][0]=s[ni][1]=s[ni][2]=s[ni][3]=0.f; }
        #pragma unroll
        for (int ks = 0; ks < 5; ks++) {
            #pragma unroll
            for (int ni = 0; ni < 8; ni++) {
                uint32_t b0 = *(const uint32_t*)&Kc[(8*ni + gr)*KSR + ks*16 + 2*t4];
                uint32_t b1 = *(const uint32_t*)&Kc[(8*ni + gr)*KSR + ks*16 + 8 + 2*t4];
                mma16h(s[ni], qf[ks][0], qf[ks][1], qf[ks][2], qf[ks][3], b0, b1);
            }
        }

        float tm0 = -1e30f, tm1 = -1e30f;
        #pragma unroll
        for (int ni = 0; ni < 8; ni++) {
            tm0 = fmaxf(tm0, fmaxf(s[ni][0], s[ni][1]));
            tm1 = fmaxf(tm1, fmaxf(s[ni][2], s[ni][3]));
        }
        tm0 = fmaxf(tm0, __shfl_xor_sync(~0u, tm0, 1));
        tm0 = fmaxf(tm0, __shfl_xor_sync(~0u, tm0, 2));
        tm1 = fmaxf(tm1, __shfl_xor_sync(~0u, tm1, 1));
        tm1 = fmaxf(tm1, __shfl_xor_sync(~0u, tm1, 2));
        float mn0 = fmaxf(m0v, tm0), mn1 = fmaxf(m1v, tm1);
        float al0 = __expf(m0v - mn0), al1 = __expf(m1v - mn1);
        m0v = mn0; m1v = mn1;
        float ts0 = 0.f, ts1 = 0.f;
        #pragma unroll
        for (int ni = 0; ni < 8; ni++) {
            s[ni][0] = __expf(s[ni][0] - mn0);
            s[ni][1] = __expf(s[ni][1] - mn0);
            s[ni][2] = __expf(s[ni][2] - mn1);
            s[ni][3] = __expf(s[ni][3] - mn1);
            ts0 += s[ni][0] + s[ni][1];
            ts1 += s[ni][2] + s[ni][3];
        }
        ts0 += __shfl_xor_sync(~0u, ts0, 1); ts0 += __shfl_xor_sync(~0u, ts0, 2);
        ts1 += __shfl_xor_sync(~0u, ts1, 1); ts1 += __shfl_xor_sync(~0u, ts1, 2);
        l0 = l0*al0 + ts0;
        l1 = l1*al1 + ts1;
        #pragma unroll
        for (int ni = 0; ni < 10; ni++) {
            oa[ni][0] *= al0; oa[ni][1] *= al0;
            oa[ni][2] *= al1; oa[ni][3] *= al1;
        }

        #pragma unroll
        for (int ks = 0; ks < 4; ks++) {
            uint32_t a0 = hpack(s[2*ks][0],   s[2*ks][1]);
            uint32_t a1 = hpack(s[2*ks][2],   s[2*ks][3]);
            uint32_t a2 = hpack(s[2*ks+1][0], s[2*ks+1][1]);
            uint32_t a3 = hpack(s[2*ks+1][2], s[2*ks+1][3]);
            #pragma unroll
            for (int ni = 0; ni < 10; ni++) {
                uint32_t b0 = *(const uint32_t*)&Vc[(8*ni + gr)*VSR + ks*16 + 2*t4];
                uint32_t b1 = *(const uint32_t*)&Vc[(8*ni + gr)*VSR + ks*16 + 8 + 2*t4];
                mma16h(oa[ni], a0, a1, a2, a3, b0, b1);
            }
        }
        __syncthreads();
    }

    float inv0 = 1.f / l0, inv1 = 1.f / l1;
    __half* Ob = O + ((size_t)(b*HW + q0 + w*16))*CCH + h*DH;
    #pragma unroll
    for (int ni = 0; ni < 10; ni++) {
        *(__half2*)(Ob + (size_t)gr*CCH + 8*ni + 2*t4) =
            __floats2half2_rn(oa[ni][0]*inv0, oa[ni][1]*inv0);
        *(__half2*)(Ob + (size_t)(gr+8)*CCH + 8*ni + 2*t4) =
            __floats2half2_rn(oa[ni][2]*inv1, oa[ni][3]*inv1);
    }
}

// ---------------- tiled fp16 cross-attention (SK=77 padded to 80), 2 CTA/SM ----------------
__global__ __launch_bounds__(256, 2)
void xattn_h(const __half* __restrict__ Q, const __half* __restrict__ KV,
             __half* __restrict__ O) {
    __shared__ __half Ks[80*KSR];
    __shared__ __half Vt[80*KSR];

    int tid = threadIdx.x, lane = tid & 31, w = tid >> 5;
    int z = blockIdx.y;
    int b = z >> 3, h = z & 7;
    int q0 = blockIdx.x * 128;
    int gr = lane >> 2, t4 = lane & 3;

    for (int i = tid; i < 80*KSR; i += 256) { Ks[i] = __half(0.f); Vt[i] = __half(0.f); }
    __syncthreads();

    const __half* kc = KV + (size_t)(b*SKCTX)*(2*CCH) + h*DH;
    const __half* vc = kc + CCH;
    for (int idx = tid; idx < SKCTX*40; idx += 256) {
        int key = idx / 40, d2 = idx - key*40;
        __half2 kv = *(const __half2*)(kc + (size_t)key*(2*CCH) + 2*d2);
        __half2 vv = *(const __half2*)(vc + (size_t)key*(2*CCH) + 2*d2);
        *(__half2*)&Ks[key*KSR + 2*d2] = kv;
        Vt[(2*d2)*KSR + key]   = vv.x;
        Vt[(2*d2+1)*KSR + key] = vv.y;
    }
    __syncthreads();

    const __half2 qs2 = __float2half2_rn(0.1118033988749895f);
    uint32_t qf[5][4];
    {
        const __half* qp  = Q + (size_t)(b*HW + q0 + w*16 + gr)*CCH + h*DH;
        const __half* qp8 = qp + 8*CCH;
        #pragma unroll
        for (int ks = 0; ks < 5; ks++) {
            __half2 v0 = __hmul2(*(const __half2*)(qp  + ks*16 + 2*t4),     qs2);
            __half2 v1 = __hmul2(*(const __half2*)(qp8 + ks*16 + 2*t4),     qs2);
            __half2 v2 = __hmul2(*(const __half2*)(qp  + ks*16 + 8 + 2*t4), qs2);
            __half2 v3 = __hmul2(*(const __half2*)(qp8 + ks*16 + 8 + 2*t4), qs2);
            qf[ks][0] = *(uint32_t*)&v0; qf[ks][1] = *(uint32_t*)&v1;
            qf[ks][2] = *(uint32_t*)&v2; qf[ks][3] = *(uint32_t*)&v3;
        }
    }

    float s[10][4];
    #pragma unroll
    for (int ni = 0; ni < 10; ni++) { s[ni][0]=s[ni][1]=s[ni][2]=s[ni][3]=0.f; }
    #pragma unroll
    for (int ks = 0; ks < 5; ks++) {
        #pragma unroll
        for (int ni = 0; ni < 10; ni++) {
            uint32_t b0 = *(const uint32_t*)&Ks[(8*ni + gr)*KSR + ks*16 + 2*t4];
            uint32_t b1 = *(const uint32_t*)&Ks[(8*ni + gr)*KSR + ks*16 + 8 + 2*t4];
            mma16h(s[ni], qf[ks][0], qf[ks][1], qf[ks][2], qf[ks][3], b0, b1);
        }
    }
    if (t4 == 3) { s[9][0] = -1e30f; s[9][2] = -1e30f; }
    if (t4 >= 2) { s[9][1] = -1e30f; s[9][3] = -1e30f; }

    float m0 = -1e30f, m1 = -1e30f;
    #pragma unroll
    for (int ni = 0; ni < 10; ni++) {
        m0 = fmaxf(m0, fmaxf(s[ni][0], s[ni][1]));
        m1 = fmaxf(m1, fmaxf(s[ni][2], s[ni][3]));
    }
    m0 = fmaxf(m0, __shfl_xor_sync(~0u, m0, 1));
    m0 = fmaxf(m0, __shfl_xor_sync(~0u, m0, 2));
    m1 = fmaxf(m1, __shfl_xor_sync(~0u, m1, 1));
    m1 = fmaxf(m1, __shfl_xor_sync(~0u, m1, 2));
    float l0 = 0.f, l1 = 0.f;
    #pragma unroll
    for (int ni = 0; ni < 10; ni++) {
        s[ni][0] = __expf(s[ni][0] - m0);
        s[ni][1] = __expf(s[ni][1] - m0);
        s[ni][2] = __expf(s[ni][2] - m1);
        s[ni][3] = __expf(s[ni][3] - m1);
        l0 += s[ni][0] + s[ni][1];
        l1 += s[ni][2] + s[ni][3];
    }
    l0 += __shfl_xor_sync(~0u, l0, 1); l0 += __shfl_xor_sync(~0u, l0, 2);
    l1 += __shfl_xor_sync(~0u, l1, 1); l1 += __shfl_xor_sync(~0u, l1, 2);

    float oa[10][4];
    #pragma unroll
    for (int ni = 0; ni < 10; ni++) { oa[ni][0]=oa[ni][1]=oa[ni][2]=oa[ni][3]=0.f; }
    #pragma unroll
    for (int ks = 0; ks < 5; ks++) {
        uint32_t a0 = hpack(s[2*ks][0],   s[2*ks][1]);
        uint32_t a1 = hpack(s[2*ks][2],   s[2*ks][3]);
        uint32_t a2 = hpack(s[2*ks+1][0], s[2*ks+1][1]);
        uint32_t a3 = hpack(s[2*ks+1][2], s[2*ks+1][3]);
        #pragma unroll
        for (int ni = 0; ni < 10; ni++) {
            uint32_t b0 = *(const uint32_t*)&Vt[(8*ni + gr)*KSR + ks*16 + 2*t4];
            uint32_t b1 = *(const uint32_t*)&Vt[(8*ni + gr)*KSR + ks*16 + 8 + 2*t4];
            mma16h(oa[ni], a0, a1, a2, a3, b0, b1);
        }
    }

    float inv0 = 1.f / l0, inv1 = 1.f / l1;
    __half* Ob = O + ((size_t)(b*HW + q0 + w*16))*CCH + h*DH;
    #pragma unroll
    for (int ni = 0; ni < 10; ni++) {
        *(__half2*)(Ob + (size_t)gr*CCH + 8*ni + 2*t4) =
            __floats2half2_rn(oa[ni][0]*inv0, oa[ni][1]*inv0);
        *(__half2*)(Ob + (size_t)(gr+8)*CCH + 8*ni + 2*t4) =
            __floats2half2_rn(oa[ni][2]*inv1, oa[ni][3]*inv1);
    }
}

// ---------------- host launch ----------------
extern "C" void kernel_launch(void* const* d_in, const int* in_sizes, int n_in,
                              void* d_out, int out_size) {
    const float* x        = (const float*)d_in[0];
    const float* context  = (const float*)d_in[1];
    const float* gn_s     = (const float*)d_in[2];
    const float* gn_b     = (const float*)d_in[3];
    const float* conv1_w  = (const float*)d_in[4];
    const float* conv1_b  = (const float*)d_in[5];
    const float* ln1_s    = (const float*)d_in[6];
    const float* ln1_b    = (const float*)d_in[7];
    const float* sa_in_w  = (const float*)d_in[8];
    const float* sa_out_w = (const float*)d_in[9];
    const float* sa_out_b = (const float*)d_in[10];
    const float* ln2_s    = (const float*)d_in[11];
    const float* ln2_b    = (const float*)d_in[12];
    const float* ca_q_w   = (const float*)d_in[13];
    const float* ca_k_w   = (const float*)d_in[14];
    const float* ca_v_w   = (const float*)d_in[15];
    const float* ca_out_w = (const float*)d_in[16];
    const float* ca_out_b = (const float*)d_in[17];
    const float* ln3_s    = (const float*)d_in[18];
    const float* ln3_b    = (const float*)d_in[19];
    const float* lin1_w   = (const float*)d_in[20];
    const float* lin1_b   = (const float*)d_in[21];
    const float* lin2_w   = (const float*)d_in[22];
    const float* lin2_b   = (const float*)d_in[23];
    const float* co_w     = (const float*)d_in[24];
    const float* co_b     = (const float*)d_in[25];
    float* out = (float*)d_out;

    float *xseq, *lin1bi;
    __half *hgn, *ht, *hattn, *hctx, *hkv, *hffg, *hx, *hqkv, *hvt, *hw;
    cudaGetSymbolAddress((void**)&xseq, g_xseq);
    cudaGetSymbolAddress((void**)&lin1bi, g_lin1bi);
    cudaGetSymbolAddress((void**)&hgn,  h_gn);
    cudaGetSymbolAddress((void**)&ht,   h_t);
    cudaGetSymbolAddress((void**)&hattn,h_attn);
    cudaGetSymbolAddress((void**)&hctx, h_ctx);
    cudaGetSymbolAddress((void**)&hkv,  h_kv);
    cudaGetSymbolAddress((void**)&hffg, h_ffg);
    cudaGetSymbolAddress((void**)&hx,   h_x);
    cudaGetSymbolAddress((void**)&hqkv, h_qkv);
    cudaGetSymbolAddress((void**)&hvt,  h_vt);
    cudaGetSymbolAddress((void**)&hw,   h_w);

    __half* sa_in_wT  = hw;
    __half* sa_out_wT = sa_in_wT  + 1920*640;
    __half* ca_q_wT   = sa_out_wT + 640*640;
    __half* ca_k_wT   = ca_q_wT   + 640*640;
    __half* ca_v_wT   = ca_k_wT   + 640*512;
    __half* ca_out_wT = ca_v_wT   + 640*512;
    __half* lin1_wT   = ca_out_wT + 640*640;
    __half* lin2_wT   = lin1_wT   + 5120*640;
    __half* conv1_wh  = lin2_wT   + 640*2560;
    __half* co_wh     = conv1_wh  + 640*640;
    (void)ca_v_wT;

    cudaFuncSetAttribute(gemm_h<0,64>,  cudaFuncAttributeMaxDynamicSharedMemorySize, SMEM_FOR(64));
    cudaFuncSetAttribute(gemm_h<0,128>, cudaFuncAttributeMaxDynamicSharedMemorySize, SMEM_FOR(128));
    cudaFuncSetAttribute(gemm_h<1,128>, cudaFuncAttributeMaxDynamicSharedMemorySize, SMEM_FOR(128));
    cudaFuncSetAttribute(gemm_h<2,128>, cudaFuncAttributeMaxDynamicSharedMemorySize, SMEM_FOR(128));
    cudaFuncSetAttribute(gemm_h<3,128>, cudaFuncAttributeMaxDynamicSharedMemorySize, SMEM_FOR(128));
    cudaFuncSetAttribute(gemm_dual,     cudaFuncAttributeMaxDynamicSharedMemorySize, SMEM_FOR(64));

    const int M = NB * HW;      // 8192
    const int MC = NB * SKCTX;  // 616
    dim3 tblk(32, 8);
    dim3 tgrid(HW/32, CCH/32, NB);
    auto g128 = [](int N_, int M_) { return dim3(N_/128, (M_+127)/128); };
    auto g64  = [](int N_, int M_) { return dim3(N_/128, (M_+63)/64); };

    // 0. weight prep
    {
        W8 ws;
        auto mk = [](const float* s, __half* d, int K, int N, int off, int il) {
            WSeg w; w.src = s; w.dst = d; w.K = K; w.N = N;
            w.tilesX = N/32; w.tileOff = off; w.ileave = il; return w;
        };
        int off = 0;
        ws.w[0] = mk(sa_in_w,  sa_in_wT,  CCH, 3*CCH, off, 0); off += (3*CCH/32)*(CCH/32);
        ws.w[1] = mk(sa_out_w, sa_out_wT, CCH, CCH,   off, 0); off += (CCH/32)*(CCH/32);
        ws.w[2] = mk(ca_q_w,   ca_q_wT,   CCH, CCH,   off, 0); off += (CCH/32)*(CCH/32);
        ws.w[3] = mk(ca_k_w,   ca_k_wT,   DCTX, CCH,  off, 0); off += (CCH/32)*(DCTX/32);
        ws.w[4] = mk(ca_v_w,   ca_v_wT,   DCTX, CCH,  off, 0); off += (CCH/32)*(DCTX/32);
        ws.w[5] = mk(ca_out_w, ca_out_wT, CCH, CCH,   off, 0); off += (CCH/32)*(CCH/32);
        ws.w[6] = mk(lin1_w,   lin1_wT,   CCH, 8*CCH, off, 1); off += (8*CCH/32)*(CCH/32);
        ws.w[7] = mk(lin2_w,   lin2_wT,   4*CCH, CCH, off, 0); off += (CCH/32)*(4*CCH/32);
        wtrans_all<<<off, tblk>>>(ws);
    }
    {
        int e0 = CCH*CCH/4, e1 = CCH*CCH/4, e2 = MC*DCTX/4, e3 = CCH;
        cvt_all<<<(e0+e1+e2+e3 + 255)/256, 256>>>(conv1_w, conv1_wh, e0,
                                                  co_w, co_wh, e1,
                                                  context, hctx, e2,
                                                  lin1_b, lin1bi, e3);
    }

    // 1. GroupNorm + transpose
    gn_stats<<<NB*GRP, 1024>>>(x);
    gn_apply<<<tgrid, tblk>>>(x, gn_s, gn_b);

    // 2. conv1 (64-row tiles: 640 CTAs)
    gemm_h<0,64><<<g64(CCH, M), 256, SMEM_FOR(64)>>>(hgn, CCH, conv1_wh, conv1_b, nullptr,
                                                     xseq, nullptr, CCH, M, CCH, CCH);

    // 3. self-attention
    layernorm<<<M, 160>>>(xseq, ln1_s, ln1_b, ht);
    gemm_h<3,128><<<g128(3*CCH, M), 256, SMEM_FOR(128)>>>(ht, CCH, sa_in_wT, nullptr, nullptr,
                                                          (float*)hvt, hqkv, 3*CCH, M, 3*CCH, CCH);
    flash_h<<<dim3(HW/128, NB*NH), 256>>>(hqkv, hvt, hattn);
    gemm_h<0,64><<<g64(CCH, M), 256, SMEM_FOR(64)>>>(hattn, CCH, sa_out_wT, sa_out_b, xseq,
                                                     xseq, nullptr, CCH, M, CCH, CCH);

    // 4. cross-attention: q-proj + kv-proj fused (64-row tiles: 640+100 CTAs)
    layernorm<<<M, 160>>>(xseq, ln2_s, ln2_b, ht);
    {
        int nq  = (CCH/128) * (M/64);                 // 5*128 = 640
        int nkv = (2*CCH/128) * ((MC + 63)/64);       // 10*10 = 100
        gemm_dual<<<nq + nkv, 256, SMEM_FOR(64)>>>(
            ht, CCH, ca_q_wT, hqkv, CCH, M, CCH, CCH, CCH/128, nq,
            hctx, DCTX, ca_k_wT, hkv, 2*CCH, MC, 2*CCH, DCTX, 2*CCH/128);
    }
    xattn_h<<<dim3(HW/128, NB*NH), 256>>>(hqkv, hkv, hattn);
    gemm_h<0,64><<<g64(CCH, M), 256, SMEM_FOR(64)>>>(hattn, CCH, ca_out_wT, ca_out_b, xseq,
                                                     xseq, nullptr, CCH, M, CCH, CCH);

    // 5. GeGLU FFN
    layernorm<<<M, 160>>>(xseq, ln3_s, ln3_b, ht);
    gemm_h<1,128><<<g128(8*CCH, M), 256, SMEM_FOR(128)>>>(ht, CCH, lin1_wT, lin1bi, nullptr,
                                                          nullptr, hffg, 4*CCH, M, 8*CCH, CCH);
    gemm_h<0,64><<<g64(CCH, M), 256, SMEM_FOR(64)>>>(hffg, 4*CCH, lin2_wT, lin2_b, xseq,
                                                     nullptr, hx, CCH, M, CCH, 4*CCH);

    // 6. final conv + long residual
    gemm_h<2,128><<<g128(CCH, M), 256, SMEM_FOR(128)>>>(hx, CCH, co_wh, co_b, x,
                                                        out, nullptr, CCH, M, CCH, CCH);
}

// round 17
// speedup vs baseline: 1.0249x; 1.0249x over previous
#include <cuda_runtime.h>
#include <cuda_fp16.h>
#include <math.h>
#include <stdint.h>

#define NB    8
#define CCH   640
#define HW    1024
#define NH    8
#define DH    80
#define DCTX  512
#define GRP   32
#define CPG   20
#define SKCTX 77

// ---------------- fp32 scratch ----------------
__device__ float  g_xseq [NB*HW*CCH];
__device__ float  g_gnstat[NB*GRP*2];
__device__ float  g_lin1bi[8*CCH];
// ---------------- fp16 scratch ----------------
__device__ __half h_gn  [NB*HW*CCH];
__device__ __half h_t   [NB*HW*CCH];
__device__ __half h_attn[NB*HW*CCH];
__device__ __half h_ctx [NB*SKCTX*DCTX];
__device__ __half h_kv  [NB*SKCTX*2*CCH];
__device__ __half h_ffg [NB*HW*4*CCH];
__device__ __half h_x   [NB*HW*CCH];
__device__ __half h_qkv [NB*HW*3*CCH];
__device__ __half h_vt  [NB*CCH*HW];
__device__ __half h_w   [8847360];       // all weights, fp16, [N,K]

// ---------------- GroupNorm stats ----------------
__global__ __launch_bounds__(1024)
void gn_stats(const float* __restrict__ x) {
    int ng = blockIdx.x;
    int n = ng / GRP, g = ng % GRP;
    const float4* base = (const float4*)(x + ((size_t)n*CCH + (size_t)g*CPG) * HW);
    float s = 0.f, s2 = 0.f;
    for (int i = threadIdx.x; i < CPG*HW/4; i += 1024) {
        float4 v = base[i];
        s  += v.x + v.y + v.z + v.w;
        s2 += v.x*v.x + v.y*v.y + v.z*v.z + v.w*v.w;
    }
    __shared__ float rs[1024], rq[1024];
    rs[threadIdx.x] = s; rq[threadIdx.x] = s2;
    __syncthreads();
    for (int o = 512; o > 0; o >>= 1) {
        if (threadIdx.x < o) { rs[threadIdx.x] += rs[threadIdx.x+o]; rq[threadIdx.x] += rq[threadIdx.x+o]; }
        __syncthreads();
    }
    if (threadIdx.x == 0) {
        float inv_n = 1.f / (float)(CPG*HW);
        float mu  = rs[0] * inv_n;
        float var = rq[0] * inv_n - mu*mu;
        g_gnstat[ng*2]   = mu;
        g_gnstat[ng*2+1] = rsqrtf(var + 1e-6f);
    }
}

// ---------------- GroupNorm apply + transpose -> fp16 [n,p,c] ----------------
__global__ void gn_apply(const float* __restrict__ x,
                         const float* __restrict__ s, const float* __restrict__ b) {
    __shared__ float tile[32][33];
    int n = blockIdx.z;
    int p0 = blockIdx.x*32, c0 = blockIdx.y*32;
    int tx = threadIdx.x, ty = threadIdx.y;
    #pragma unroll
    for (int i = 0; i < 4; i++) {
        int c = c0 + ty + i*8;
        int ng = n*GRP + c / CPG;
        float mu = g_gnstat[ng*2], is = g_gnstat[ng*2+1];
        float v = x[((size_t)n*CCH + c)*HW + p0 + tx];
        tile[ty + i*8][tx] = (v - mu) * is * s[c] + b[c];
    }
    __syncthreads();
    #pragma unroll
    for (int i = 0; i < 4; i++) {
        int p = p0 + ty + i*8;
        h_gn[((size_t)n*HW + p)*CCH + c0 + tx] = __float2half(tile[tx][ty + i*8]);
    }
}

// ---------------- merged weight transpose+convert ----------------
struct WSeg { const float* src; __half* dst; int K, N, tilesX, tileOff, ileave; };
struct W8 { WSeg w[8]; };
__global__ void wtrans_all(W8 ws) {
    __shared__ float t[32][33];
    int bid = blockIdx.x;
    int si = 0;
    #pragma unroll
    for (int i = 1; i < 8; i++)
        if (bid >= ws.w[i].tileOff) si = i;
    WSeg sg = ws.w[si];
    int local = bid - sg.tileOff;
    int n0 = (local % sg.tilesX) * 32;
    int k0 = (local / sg.tilesX) * 32;
    int tx = threadIdx.x, ty = threadIdx.y;
    #pragma unroll
    for (int i = 0; i < 4; i++)
        t[ty + i*8][tx] = sg.src[(size_t)(k0 + ty + i*8)*sg.N + n0 + tx];
    __syncthreads();
    int half = sg.N >> 1;
    #pragma unroll
    for (int i = 0; i < 4; i++) {
        int r = n0 + ty + i*8;
        int rr = sg.ileave ? ((r < half) ? 2*r : 2*(r - half) + 1) : r;
        sg.dst[(size_t)rr*sg.K + k0 + tx] = __float2half(t[tx][ty + i*8]);
    }
}

// ---------------- merged converts + lin1 bias interleave ----------------
__global__ void cvt_all(const float* s0, __half* d0, int e0,
                        const float* s1, __half* d1, int e1,
                        const float* s2, __half* d2, int e2,
                        const float* b,  float* bi,  int e3) {
    int i = blockIdx.x * 256 + threadIdx.x;
    if (i >= e0 + e1 + e2) {
        int off = i - e0 - e1 - e2;
        if (off < e3) {
            int j = off * 4;
            float4 a = *(const float4*)(b + j);
            float4 g = *(const float4*)(b + j + 4*CCH);
            *(float4*)(bi + 2*j)     = make_float4(a.x, g.x, a.y, g.y);
            *(float4*)(bi + 2*j + 4) = make_float4(a.z, g.z, a.w, g.w);
        }
        return;
    }
    const float* s; __half* d; int off;
    if (i < e0) { s = s0; d = d0; off = i; }
    else if (i < e0 + e1) { s = s1; d = d1; off = i - e0; }
    else { s = s2; d = d2; off = i - e0 - e1; }
    float4 v = ((const float4*)s)[off];
    union { uint2 u; __half2 h[2]; } pk;
    pk.h[0] = __floats2half2_rn(v.x, v.y);
    pk.h[1] = __floats2half2_rn(v.z, v.w);
    ((uint2*)d)[off] = pk.u;
}

// ---------------- LayerNorm fp32 in -> fp16 out ----------------
__global__ __launch_bounds__(160)
void layernorm(const float* __restrict__ in,
               const float* __restrict__ s, const float* __restrict__ b,
               __half* __restrict__ out) {
    int row = blockIdx.x;
    int tid = threadIdx.x;
    const float4* r4 = (const float4*)(in + (size_t)row * CCH);
    float4 v = r4[tid];
    float sum = v.x + v.y + v.z + v.w;
    float sq  = v.x*v.x + v.y*v.y + v.z*v.z + v.w*v.w;
    #pragma unroll
    for (int o = 16; o > 0; o >>= 1) {
        sum += __shfl_xor_sync(~0u, sum, o);
        sq  += __shfl_xor_sync(~0u, sq,  o);
    }
    __shared__ float ws[5], wq[5];
    int w = tid >> 5;
    if ((tid & 31) == 0) { ws[w] = sum; wq[w] = sq; }
    __syncthreads();
    sum = ws[0] + ws[1] + ws[2] + ws[3] + ws[4];
    sq  = wq[0] + wq[1] + wq[2] + wq[3] + wq[4];
    float mu  = sum / (float)CCH;
    float inv = rsqrtf(sq / (float)CCH - mu*mu + 1e-5f);
    float4 sc = ((const float4*)s)[tid];
    float4 bb = ((const float4*)b)[tid];
    union { uint2 u; __half2 h[2]; } pk;
    pk.h[0] = __floats2half2_rn((v.x - mu) * inv * sc.x + bb.x, (v.y - mu) * inv * sc.y + bb.y);
    pk.h[1] = __floats2half2_rn((v.z - mu) * inv * sc.z + bb.z, (v.w - mu) * inv * sc.w + bb.w);
    ((uint2*)(out + (size_t)row * CCH))[tid] = pk.u;
}

// ---------------- mma / cp.async helpers ----------------
__device__ __forceinline__ void mma16h(float c[4], uint32_t a0, uint32_t a1, uint32_t a2, uint32_t a3,
                                       uint32_t b0, uint32_t b1) {
    asm volatile("mma.sync.aligned.m16n8k16.row.col.f32.f16.f16.f32 "
        "{%0,%1,%2,%3}, {%4,%5,%6,%7}, {%8,%9}, {%0,%1,%2,%3};"
        : "+f"(c[0]), "+f"(c[1]), "+f"(c[2]), "+f"(c[3])
        : "r"(a0), "r"(a1), "r"(a2), "r"(a3), "r"(b0), "r"(b1));
}
__device__ __forceinline__ void ldsm4(uint32_t r[4], uint32_t addr) {
    asm volatile("ldmatrix.sync.aligned.m8n8.x4.shared.b16 {%0,%1,%2,%3}, [%4];"
        : "=r"(r[0]), "=r"(r[1]), "=r"(r[2]), "=r"(r[3]) : "r"(addr));
}
__device__ __forceinline__ void cpa16(void* dst, const void* src, bool valid) {
    uint32_t d = (uint32_t)__cvta_generic_to_shared(dst);
    int sz = valid ? 16 : 0;
    asm volatile("cp.async.cg.shared.global [%0], [%1], 16, %2;" :: "r"(d), "l"(src), "r"(sz));
}
#define CP_COMMIT() asm volatile("cp.async.commit_group;")
#define CP_WAIT1()  asm volatile("cp.async.wait_group 1;")
__device__ __forceinline__ uint32_t hpack(float a, float b) {
    __half2 h = __floats2half2_rn(a, b);
    return *(uint32_t*)&h;
}

// ---------------- fp16 GEMM core: MBx128x64 tiles, NSTG-stage cp.async, all-ldmatrix ----------------
// MODE 0: normal  MODE 1: geglu epilogue  MODE 2: NCHW transpose+residual
// MODE 3: fp16 out + transposed V side-store  (MODE 1/2/3 require MB=128)
#define RS36 36
#define SMEM_FOR(MB, NSTG) ((NSTG)*((MB)+128)*RS36*4)
template<int MODE, int MB, int NSTG>
__device__ __forceinline__
void gemm_core(uint32_t* sm, int bm, int bn,
               const __half* __restrict__ A, int lda,
               const __half* __restrict__ B,
               const float* __restrict__ bias,
               const float* __restrict__ res,
               float* __restrict__ C, __half* __restrict__ Ch, int ldc,
               int M, int N, int K) {
    constexpr int NMI  = MB / 32;
    constexpr int BUFA = MB * RS36;
    constexpr int BUFB = 128 * RS36;
    uint32_t* As = sm;
    uint32_t* Bs = sm + NSTG*BUFA;
    uint32_t a_u32 = (uint32_t)__cvta_generic_to_shared(As);
    uint32_t b_u32 = (uint32_t)__cvta_generic_to_shared(Bs);

    int tid = threadIdx.x;
    int lane = tid & 31, warp = tid >> 5;
    int gr = lane >> 2, t4 = lane & 3;
    int wm = (warp >> 2) * (MB/2), wn = (warp & 3) * 32;

    uint32_t lds_off  = (uint32_t)((lane & 15) * (RS36*4) + ((lane >> 4) << 4));
    uint32_t ldsb_off = (uint32_t)(((lane & 7) + ((lane >> 4) << 3)) * (RS36*4)
                                   + (((lane >> 3) & 1) << 4));

    auto stage = [&](int kt, int buf) {
        #pragma unroll
        for (int i = 0; i < MB/32; i++) {
            int c = tid + i*256;
            int row = c >> 3, seg = c & 7;
            int gm = bm + row;
            cpa16(As + buf*BUFA + row*RS36 + seg*4,
                  A + ((size_t)(gm < M ? gm : 0))*lda + kt*64 + seg*8, gm < M);
        }
        #pragma unroll
        for (int i = 0; i < 4; i++) {
            int c = tid + i*256;
            int row = c >> 3, seg = c & 7;
            int gn = bn + row;
            cpa16(Bs + buf*BUFB + row*RS36 + seg*4,
                  B + ((size_t)(gn < N ? gn : 0))*K + kt*64 + seg*8, gn < N);
        }
    };

    float acc[NMI][4][4];
    #pragma unroll
    for (int i = 0; i < NMI; i++)
        #pragma unroll
        for (int j = 0; j < 4; j++)
            #pragma unroll
            for (int r = 0; r < 4; r++) acc[i][j][r] = 0.f;

    int nk = K >> 6;
    stage(0, 0); CP_COMMIT();
    stage(1, 1); CP_COMMIT();

    int buf = 0;
    for (int t = 0; t < nk; t++) {
        CP_WAIT1();
        __syncthreads();
        if (NSTG >= 3) {
            if (t + 2 < nk) stage(t+2, (t+2) % NSTG);
            CP_COMMIT();
        }

        uint32_t a_base = a_u32 + buf*(BUFA*4) + lds_off;
        uint32_t b_base = b_u32 + buf*(BUFB*4) + ldsb_off;

        #pragma unroll
        for (int ks = 0; ks < 4; ks++) {
            uint32_t af[NMI][4], bf[4][2];
            #pragma unroll
            for (int mi = 0; mi < NMI; mi++)
                ldsm4(af[mi], a_base + (uint32_t)((wm + mi*16)*(RS36*4) + ks*32));
            #pragma unroll
            for (int p = 0; p < 2; p++) {
                uint32_t r[4];
                ldsm4(r, b_base + (uint32_t)((wn + p*16)*(RS36*4) + ks*32));
                bf[2*p][0]   = r[0]; bf[2*p][1]   = r[1];
                bf[2*p+1][0] = r[2]; bf[2*p+1][1] = r[3];
            }
            #pragma unroll
            for (int mi = 0; mi < NMI; mi++)
                #pragma unroll
                for (int ni = 0; ni < 4; ni++)
                    mma16h(acc[mi][ni], af[mi][0], af[mi][1], af[mi][2], af[mi][3],
                           bf[ni][0], bf[ni][1]);
        }
        if (NSTG == 2) {
            __syncthreads();                 // all threads done reading buf before reuse
            if (t + 2 < nk) stage(t+2, buf);
            CP_COMMIT();
        }
        buf = (buf + 1 == NSTG) ? 0 : buf + 1;
    }

    if (MODE == 2) {
        __syncthreads();
        float* eb = (float*)sm;          // [128 cols][132]
        #pragma unroll
        for (int mi = 0; mi < NMI; mi++) {
            #pragma unroll
            for (int ni = 0; ni < 4; ni++) {
                int col_l = wn + ni*8 + t4*2;
                int col0  = bn + col_l;
                #pragma unroll
                for (int half_r = 0; half_r < 2; half_r++) {
                    int row_l = wm + mi*16 + gr + half_r*8;
                    eb[(col_l)*132 + row_l]   = acc[mi][ni][half_r*2 + 0] + bias[col0];
                    eb[(col_l+1)*132 + row_l] = acc[mi][ni][half_r*2 + 1] + bias[col0+1];
                }
            }
        }
        __syncthreads();
        int n = bm >> 10, p0 = bm & 1023;
        for (int i = tid; i < 128*32; i += 256) {
            int c = i >> 5, seg = i & 31;
            size_t off = ((size_t)(n*CCH + bn + c))*HW + p0 + seg*4;
            const float* e = eb + c*132 + seg*4;
            float4 xr = *(const float4*)(res + off);
            *(float4*)(C + off) = make_float4(e[0]+xr.x, e[1]+xr.y, e[2]+xr.z, e[3]+xr.w);
        }
        return;
    }

    if (MODE == 1) {
        __syncthreads();
        __half* eb = (__half*)sm;        // [128 rows][72]
        #pragma unroll
        for (int mi = 0; mi < NMI; mi++) {
            #pragma unroll
            for (int ni = 0; ni < 4; ni++) {
                int col_l = wn + ni*8 + t4*2;
                int col0  = bn + col_l;
                #pragma unroll
                for (int half_r = 0; half_r < 2; half_r++) {
                    int row_l = wm + mi*16 + gr + half_r*8;
                    float a = acc[mi][ni][half_r*2 + 0] + bias[col0];
                    float g = acc[mi][ni][half_r*2 + 1] + bias[col0+1];
                    float ge = 0.5f * g * (1.f + erff(g * 0.70710678118654752f));
                    eb[row_l*72 + (col_l >> 1)] = __float2half(a * ge);
                }
            }
        }
        __syncthreads();
        for (int i = tid; i < 128*8; i += 256) {
            int row = i >> 3, seg = i & 7;
            int grow = bm + row;
            if (grow < M)
                *(uint4*)(Ch + (size_t)grow*ldc + (bn >> 1) + seg*8) =
                    *(const uint4*)(eb + row*72 + seg*8);
        }
        return;
    }

    #pragma unroll
    for (int mi = 0; mi < NMI; mi++) {
        #pragma unroll
        for (int ni = 0; ni < 4; ni++) {
            int col0 = bn + wn + ni*8 + t4*2;
            #pragma unroll
            for (int half_r = 0; half_r < 2; half_r++) {
                int row = bm + wm + mi*16 + gr + half_r*8;
                if (row >= M) continue;
                float v0 = acc[mi][ni][half_r*2 + 0];
                float v1 = acc[mi][ni][half_r*2 + 1];
                if (bias) { v0 += bias[col0]; v1 += bias[col0+1]; }
                if (res) {
                    const float* rp = res + (size_t)row*ldc + col0;
                    v0 += rp[0]; v1 += rp[1];
                }
                if (MODE == 0 && C) *(float2*)(C + (size_t)row*ldc + col0) = make_float2(v0, v1);
                if (Ch) *(__half2*)(Ch + (size_t)row*ldc + col0) = __floats2half2_rn(v0, v1);
            }
        }
    }

    if (MODE == 3 && bn >= 2*CCH) {
        __syncthreads();
        __half* eb = (__half*)sm;        // [128][136]
        #pragma unroll
        for (int mi = 0; mi < NMI; mi++) {
            #pragma unroll
            for (int ni = 0; ni < 4; ni++) {
                int col_l = wn + ni*8 + t4*2;
                #pragma unroll
                for (int half_r = 0; half_r < 2; half_r++) {
                    int row_l = wm + mi*16 + gr + half_r*8;
                    eb[(col_l)*136 + row_l]   = __float2half(acc[mi][ni][half_r*2 + 0]);
                    eb[(col_l+1)*136 + row_l] = __float2half(acc[mi][ni][half_r*2 + 1]);
                }
            }
        }
        __syncthreads();
        __half* vt = (__half*)C;
        int b = bm >> 10, p0 = bm & 1023;
        int c0 = bn - 2*CCH;
        for (int i = tid; i < 128*16; i += 256) {
            int c = i >> 4, seg = i & 15;
            *(uint4*)(vt + ((size_t)(b*CCH + c0 + c))*HW + p0 + seg*8) =
                *(const uint4*)(eb + c*136 + seg*8);
        }
    }
}

// big-tile kernels: MB=128, 3-stage, 2 CTA/SM
template<int MODE>
__global__ __launch_bounds__(256, 2)
void gemm_h(const __half* __restrict__ A, int lda,
            const __half* __restrict__ B,
            const float* __restrict__ bias,
            const float* __restrict__ res,
            float* __restrict__ C, __half* __restrict__ Ch, int ldc,
            int M, int N, int K) {
    extern __shared__ uint32_t sm[];
    gemm_core<MODE, 128, 3>(sm, blockIdx.y*128, blockIdx.x*128,
                            A, lda, B, bias, res, C, Ch, ldc, M, N, K);
}

// small-tile kernel: MB=64, 2-stage, 3 CTA/SM (for N=640 projections)
__global__ __launch_bounds__(256, 3)
void gemm_s(const __half* __restrict__ A, int lda,
            const __half* __restrict__ B,
            const float* __restrict__ bias,
            const float* __restrict__ res,
            float* __restrict__ C, __half* __restrict__ Ch, int ldc,
            int M, int N, int K) {
    extern __shared__ uint32_t sm[];
    gemm_core<0, 64, 2>(sm, blockIdx.y*64, blockIdx.x*128,
                        A, lda, B, bias, res, C, Ch, ldc, M, N, K);
}

// dual GEMM (MB=64, 2-stage, 3 CTA/SM)
__global__ __launch_bounds__(256, 3)
void gemm_dual(const __half* A0, int lda0, const __half* B0, __half* Ch0, int ldc0,
               int M0, int N0, int K0, int nx0, int split,
               const __half* A1, int lda1, const __half* B1, __half* Ch1, int ldc1,
               int M1, int N1, int K1, int nx1) {
    extern __shared__ uint32_t sm[];
    int bid = blockIdx.x;
    if (bid < split) {
        gemm_core<0, 64, 2>(sm, (bid/nx0)*64, (bid%nx0)*128,
                            A0, lda0, B0, nullptr, nullptr, nullptr, Ch0, ldc0, M0, N0, K0);
    } else {
        int l = bid - split;
        gemm_core<0, 64, 2>(sm, (l/nx1)*64, (l%nx1)*128,
                            A1, lda1, B1, nullptr, nullptr, nullptr, Ch1, ldc1, M1, N1, K1);
    }
}

// ---------------- fused flash self-attention, full fp16 mma, 2 CTA/SM ----------------
#define KSR 88
#define VSR 72
__global__ __launch_bounds__(256, 2)
void flash_h(const __half* __restrict__ QKV, const __half* __restrict__ VT,
             __half* __restrict__ O) {
    constexpr int LD = 3*CCH;
    __shared__ __half Ks[2][64*KSR];
    __shared__ __half Vs[2][80*VSR];

    int tid = threadIdx.x, lane = tid & 31, w = tid >> 5;
    int z = blockIdx.y;
    int b = z >> 3, h = z & 7;
    int q0 = blockIdx.x * 128;
    int gr = lane >> 2, t4 = lane & 3;

    const __half* Kb  = QKV + ((size_t)b*HW)*LD + CCH + h*DH;
    const __half* Vtb = VT + ((size_t)b*CCH + h*DH)*HW;

    auto stage = [&](int kt, int buf) {
        #pragma unroll
        for (int i = 0; i < 3; i++) {
            int s = tid + i*256;
            if (s < 640) {
                int r = s / 10, g = s - r*10;
                cpa16(&Ks[buf][r*KSR + g*8], Kb + (size_t)(kt*64 + r)*LD + g*8, true);
            }
        }
        #pragma unroll
        for (int i = 0; i < 3; i++) {
            int s = tid + i*256;
            if (s < 640) {
                int r = s >> 3, g = s & 7;
                cpa16(&Vs[buf][r*VSR + g*8], Vtb + (size_t)r*HW + kt*64 + g*8, true);
            }
        }
    };

    stage(0, 0);
    CP_COMMIT();

    const __half2 qs2 = __float2half2_rn(0.1118033988749895f);
    uint32_t qf[5][4];
    {
        const __half* qp  = QKV + (size_t)(b*HW + q0 + w*16 + gr)*LD + h*DH;
        const __half* qp8 = qp + 8*LD;
        #pragma unroll
        for (int ks = 0; ks < 5; ks++) {
            __half2 v0 = __hmul2(*(const __half2*)(qp  + ks*16 + 2*t4),     qs2);
            __half2 v1 = __hmul2(*(const __half2*)(qp8 + ks*16 + 2*t4),     qs2);
            __half2 v2 = __hmul2(*(const __half2*)(qp  + ks*16 + 8 + 2*t4), qs2);
            __half2 v3 = __hmul2(*(const __half2*)(qp8 + ks*16 + 8 + 2*t4), qs2);
            qf[ks][0] = *(uint32_t*)&v0; qf[ks][1] = *(uint32_t*)&v1;
            qf[ks][2] = *(uint32_t*)&v2; qf[ks][3] = *(uint32_t*)&v3;
        }
    }

    float m0v = -1e30f, m1v = -1e30f, l0 = 0.f, l1 = 0.f;
    float oa[10][4];
    #pragma unroll
    for (int ni = 0; ni < 10; ni++) { oa[ni][0]=oa[ni][1]=oa[ni][2]=oa[ni][3]=0.f; }

    for (int kt = 0; kt < 16; kt++) {
        if (kt + 1 < 16) stage(kt+1, (kt+1) & 1);
        CP_COMMIT();
        CP_WAIT1();
        __syncthreads();
        const __half* Kc = Ks[kt & 1];
        const __half* Vc = Vs[kt & 1];

        float s[8][4];
        #pragma unroll
        for (int ni = 0; ni < 8; ni++) { s[ni][0]=s[ni][1]=s[ni][2]=s[ni][3]=0.f; }
        #pragma unroll
        for (int ks = 0; ks < 5; ks++) {
            #pragma unroll
            for (int ni = 0; ni < 8; ni++) {
                uint32_t b0 = *(const uint32_t*)&Kc[(8*ni + gr)*KSR + ks*16 + 2*t4];
                uint32_t b1 = *(const uint32_t*)&Kc[(8*ni + gr)*KSR + ks*16 + 8 + 2*t4];
                mma16h(s[ni], qf[ks][0], qf[ks][1], qf[ks][2], qf[ks][3], b0, b1);
            }
        }

        float tm0 = -1e30f, tm1 = -1e30f;
        #pragma unroll
        for (int ni = 0; ni < 8; ni++) {
            tm0 = fmaxf(tm0, fmaxf(s[ni][0], s[ni][1]));
            tm1 = fmaxf(tm1, fmaxf(s[ni][2], s[ni][3]));
        }
        tm0 = fmaxf(tm0, __shfl_xor_sync(~0u, tm0, 1));
        tm0 = fmaxf(tm0, __shfl_xor_sync(~0u, tm0, 2));
        tm1 = fmaxf(tm1, __shfl_xor_sync(~0u, tm1, 1));
        tm1 = fmaxf(tm1, __shfl_xor_sync(~0u, tm1, 2));
        float mn0 = fmaxf(m0v, tm0), mn1 = fmaxf(m1v, tm1);
        float al0 = __expf(m0v - mn0), al1 = __expf(m1v - mn1);
        m0v = mn0; m1v = mn1;
        float ts0 = 0.f, ts1 = 0.f;
        #pragma unroll
        for (int ni = 0; ni < 8; ni++) {
            s[ni][0] = __expf(s[ni][0] - mn0);
            s[ni][1] = __expf(s[ni][1] - mn0);
            s[ni][2] = __expf(s[ni][2] - mn1);
            s[ni][3] = __expf(s[ni][3] - mn1);
            ts0 += s[ni][0] + s[ni][1];
            ts1 += s[ni][2] + s[ni][3];
        }
        ts0 += __shfl_xor_sync(~0u, ts0, 1); ts0 += __shfl_xor_sync(~0u, ts0, 2);
        ts1 += __shfl_xor_sync(~0u, ts1, 1); ts1 += __shfl_xor_sync(~0u, ts1, 2);
        l0 = l0*al0 + ts0;
        l1 = l1*al1 + ts1;
        #pragma unroll
        for (int ni = 0; ni < 10; ni++) {
            oa[ni][0] *= al0; oa[ni][1] *= al0;
            oa[ni][2] *= al1; oa[ni][3] *= al1;
        }

        #pragma unroll
        for (int ks = 0; ks < 4; ks++) {
            uint32_t a0 = hpack(s[2*ks][0],   s[2*ks][1]);
            uint32_t a1 = hpack(s[2*ks][2],   s[2*ks][3]);
            uint32_t a2 = hpack(s[2*ks+1][0], s[2*ks+1][1]);
            uint32_t a3 = hpack(s[2*ks+1][2], s[2*ks+1][3]);
            #pragma unroll
            for (int ni = 0; ni < 10; ni++) {
                uint32_t b0 = *(const uint32_t*)&Vc[(8*ni + gr)*VSR + ks*16 + 2*t4];
                uint32_t b1 = *(const uint32_t*)&Vc[(8*ni + gr)*VSR + ks*16 + 8 + 2*t4];
                mma16h(oa[ni], a0, a1, a2, a3, b0, b1);
            }
        }
        __syncthreads();
    }

    float inv0 = 1.f / l0, inv1 = 1.f / l1;
    __half* Ob = O + ((size_t)(b*HW + q0 + w*16))*CCH + h*DH;
    #pragma unroll
    for (int ni = 0; ni < 10; ni++) {
        *(__half2*)(Ob + (size_t)gr*CCH + 8*ni + 2*t4) =
            __floats2half2_rn(oa[ni][0]*inv0, oa[ni][1]*inv0);
        *(__half2*)(Ob + (size_t)(gr+8)*CCH + 8*ni + 2*t4) =
            __floats2half2_rn(oa[ni][2]*inv1, oa[ni][3]*inv1);
    }
}

// ---------------- tiled fp16 cross-attention (SK=77 padded to 80), 2 CTA/SM ----------------
__global__ __launch_bounds__(256, 2)
void xattn_h(const __half* __restrict__ Q, const __half* __restrict__ KV,
             __half* __restrict__ O) {
    __shared__ __half Ks[80*KSR];
    __shared__ __half Vt[80*KSR];

    int tid = threadIdx.x, lane = tid & 31, w = tid >> 5;
    int z = blockIdx.y;
    int b = z >> 3, h = z & 7;
    int q0 = blockIdx.x * 128;
    int gr = lane >> 2, t4 = lane & 3;

    for (int i = tid; i < 80*KSR; i += 256) { Ks[i] = __half(0.f); Vt[i] = __half(0.f); }
    __syncthreads();

    const __half* kc = KV + (size_t)(b*SKCTX)*(2*CCH) + h*DH;
    const __half* vc = kc + CCH;
    for (int idx = tid; idx < SKCTX*40; idx += 256) {
        int key = idx / 40, d2 = idx - key*40;
        __half2 kv = *(const __half2*)(kc + (size_t)key*(2*CCH) + 2*d2);
        __half2 vv = *(const __half2*)(vc + (size_t)key*(2*CCH) + 2*d2);
        *(__half2*)&Ks[key*KSR + 2*d2] = kv;
        Vt[(2*d2)*KSR + key]   = vv.x;
        Vt[(2*d2+1)*KSR + key] = vv.y;
    }
    __syncthreads();

    const __half2 qs2 = __float2half2_rn(0.1118033988749895f);
    uint32_t qf[5][4];
    {
        const __half* qp  = Q + (size_t)(b*HW + q0 + w*16 + gr)*CCH + h*DH;
        const __half* qp8 = qp + 8*CCH;
        #pragma unroll
        for (int ks = 0; ks < 5; ks++) {
            __half2 v0 = __hmul2(*(const __half2*)(qp  + ks*16 + 2*t4),     qs2);
            __half2 v1 = __hmul2(*(const __half2*)(qp8 + ks*16 + 2*t4),     qs2);
            __half2 v2 = __hmul2(*(const __half2*)(qp  + ks*16 + 8 + 2*t4), qs2);
            __half2 v3 = __hmul2(*(const __half2*)(qp8 + ks*16 + 8 + 2*t4), qs2);
            qf[ks][0] = *(uint32_t*)&v0; qf[ks][1] = *(uint32_t*)&v1;
            qf[ks][2] = *(uint32_t*)&v2; qf[ks][3] = *(uint32_t*)&v3;
        }
    }

    float s[10][4];
    #pragma unroll
    for (int ni = 0; ni < 10; ni++) { s[ni][0]=s[ni][1]=s[ni][2]=s[ni][3]=0.f; }
    #pragma unroll
    for (int ks = 0; ks < 5; ks++) {
        #pragma unroll
        for (int ni = 0; ni < 10; ni++) {
            uint32_t b0 = *(const uint32_t*)&Ks[(8*ni + gr)*KSR + ks*16 + 2*t4];
            uint32_t b1 = *(const uint32_t*)&Ks[(8*ni + gr)*KSR + ks*16 + 8 + 2*t4];
            mma16h(s[ni], qf[ks][0], qf[ks][1], qf[ks][2], qf[ks][3], b0, b1);
        }
    }
    if (t4 == 3) { s[9][0] = -1e30f; s[9][2] = -1e30f; }
    if (t4 >= 2) { s[9][1] = -1e30f; s[9][3] = -1e30f; }

    float m0 = -1e30f, m1 = -1e30f;
    #pragma unroll
    for (int ni = 0; ni < 10; ni++) {
        m0 = fmaxf(m0, fmaxf(s[ni][0], s[ni][1]));
        m1 = fmaxf(m1, fmaxf(s[ni][2], s[ni][3]));
    }
    m0 = fmaxf(m0, __shfl_xor_sync(~0u, m0, 1));
    m0 = fmaxf(m0, __shfl_xor_sync(~0u, m0, 2));
    m1 = fmaxf(m1, __shfl_xor_sync(~0u, m1, 1));
    m1 = fmaxf(m1, __shfl_xor_sync(~0u, m1, 2));
    float l0 = 0.f, l1 = 0.f;
    #pragma unroll
    for (int ni = 0; ni < 10; ni++) {
        s[ni][0] = __expf(s[ni][0] - m0);
        s[ni][1] = __expf(s[ni][1] - m0);
        s[ni][2] = __expf(s[ni][2] - m1);
        s[ni][3] = __expf(s[ni][3] - m1);
        l0 += s[ni][0] + s[ni][1];
        l1 += s[ni][2] + s[ni][3];
    }
    l0 += __shfl_xor_sync(~0u, l0, 1); l0 += __shfl_xor_sync(~0u, l0, 2);
    l1 += __shfl_xor_sync(~0u, l1, 1); l1 += __shfl_xor_sync(~0u, l1, 2);

    float oa[10][4];
    #pragma unroll
    for (int ni = 0; ni < 10; ni++) { oa[ni][0]=oa[ni][1]=oa[ni][2]=oa[ni][3]=0.f; }
    #pragma unroll
    for (int ks = 0; ks < 5; ks++) {
        uint32_t a0 = hpack(s[2*ks][0],   s[2*ks][1]);
        uint32_t a1 = hpack(s[2*ks][2],   s[2*ks][3]);
        uint32_t a2 = hpack(s[2*ks+1][0], s[2*ks+1][1]);
        uint32_t a3 = hpack(s[2*ks+1][2], s[2*ks+1][3]);
        #pragma unroll
        for (int ni = 0; ni < 10; ni++) {
            uint32_t b0 = *(const uint32_t*)&Vt[(8*ni + gr)*KSR + ks*16 + 2*t4];
            uint32_t b1 = *(const uint32_t*)&Vt[(8*ni + gr)*KSR + ks*16 + 8 + 2*t4];
            mma16h(oa[ni], a0, a1, a2, a3, b0, b1);
        }
    }

    float inv0 = 1.f / l0, inv1 = 1.f / l1;
    __half* Ob = O + ((size_t)(b*HW + q0 + w*16))*CCH + h*DH;
    #pragma unroll
    for (int ni = 0; ni < 10; ni++) {
        *(__half2*)(Ob + (size_t)gr*CCH + 8*ni + 2*t4) =
            __floats2half2_rn(oa[ni][0]*inv0, oa[ni][1]*inv0);
        *(__half2*)(Ob + (size_t)(gr+8)*CCH + 8*ni + 2*t4) =
            __floats2half2_rn(oa[ni][2]*inv1, oa[ni][3]*inv1);
    }
}

// ---------------- host launch ----------------
extern "C" void kernel_launch(void* const* d_in, const int* in_sizes, int n_in,
                              void* d_out, int out_size) {
    const float* x        = (const float*)d_in[0];
    const float* context  = (const float*)d_in[1];
    const float* gn_s     = (const float*)d_in[2];
    const float* gn_b     = (const float*)d_in[3];
    const float* conv1_w  = (const float*)d_in[4];
    const float* conv1_b  = (const float*)d_in[5];
    const float* ln1_s    = (const float*)d_in[6];
    const float* ln1_b    = (const float*)d_in[7];
    const float* sa_in_w  = (const float*)d_in[8];
    const float* sa_out_w = (const float*)d_in[9];
    const float* sa_out_b = (const float*)d_in[10];
    const float* ln2_s    = (const float*)d_in[11];
    const float* ln2_b    = (const float*)d_in[12];
    const float* ca_q_w   = (const float*)d_in[13];
    const float* ca_k_w   = (const float*)d_in[14];
    const float* ca_v_w   = (const float*)d_in[15];
    const float* ca_out_w = (const float*)d_in[16];
    const float* ca_out_b = (const float*)d_in[17];
    const float* ln3_s    = (const float*)d_in[18];
    const float* ln3_b    = (const float*)d_in[19];
    const float* lin1_w   = (const float*)d_in[20];
    const float* lin1_b   = (const float*)d_in[21];
    const float* lin2_w   = (const float*)d_in[22];
    const float* lin2_b   = (const float*)d_in[23];
    const float* co_w     = (const float*)d_in[24];
    const float* co_b     = (const float*)d_in[25];
    float* out = (float*)d_out;

    float *xseq, *lin1bi;
    __half *hgn, *ht, *hattn, *hctx, *hkv, *hffg, *hx, *hqkv, *hvt, *hw;
    cudaGetSymbolAddress((void**)&xseq, g_xseq);
    cudaGetSymbolAddress((void**)&lin1bi, g_lin1bi);
    cudaGetSymbolAddress((void**)&hgn,  h_gn);
    cudaGetSymbolAddress((void**)&ht,   h_t);
    cudaGetSymbolAddress((void**)&hattn,h_attn);
    cudaGetSymbolAddress((void**)&hctx, h_ctx);
    cudaGetSymbolAddress((void**)&hkv,  h_kv);
    cudaGetSymbolAddress((void**)&hffg, h_ffg);
    cudaGetSymbolAddress((void**)&hx,   h_x);
    cudaGetSymbolAddress((void**)&hqkv, h_qkv);
    cudaGetSymbolAddress((void**)&hvt,  h_vt);
    cudaGetSymbolAddress((void**)&hw,   h_w);

    __half* sa_in_wT  = hw;
    __half* sa_out_wT = sa_in_wT  + 1920*640;
    __half* ca_q_wT   = sa_out_wT + 640*640;
    __half* ca_k_wT   = ca_q_wT   + 640*640;
    __half* ca_v_wT   = ca_k_wT   + 640*512;
    __half* ca_out_wT = ca_v_wT   + 640*512;
    __half* lin1_wT   = ca_out_wT + 640*640;
    __half* lin2_wT   = lin1_wT   + 5120*640;
    __half* conv1_wh  = lin2_wT   + 640*2560;
    __half* co_wh     = conv1_wh  + 640*640;
    (void)ca_v_wT;

    cudaFuncSetAttribute(gemm_s,     cudaFuncAttributeMaxDynamicSharedMemorySize, SMEM_FOR(64,2));
    cudaFuncSetAttribute(gemm_h<0>,  cudaFuncAttributeMaxDynamicSharedMemorySize, SMEM_FOR(128,3));
    cudaFuncSetAttribute(gemm_h<1>,  cudaFuncAttributeMaxDynamicSharedMemorySize, SMEM_FOR(128,3));
    cudaFuncSetAttribute(gemm_h<2>,  cudaFuncAttributeMaxDynamicSharedMemorySize, SMEM_FOR(128,3));
    cudaFuncSetAttribute(gemm_h<3>,  cudaFuncAttributeMaxDynamicSharedMemorySize, SMEM_FOR(128,3));
    cudaFuncSetAttribute(gemm_dual,  cudaFuncAttributeMaxDynamicSharedMemorySize, SMEM_FOR(64,2));

    const int M = NB * HW;      // 8192
    const int MC = NB * SKCTX;  // 616
    dim3 tblk(32, 8);
    dim3 tgrid(HW/32, CCH/32, NB);
    auto g128 = [](int N_, int M_) { return dim3(N_/128, (M_+127)/128); };
    auto g64  = [](int N_, int M_) { return dim3(N_/128, (M_+63)/64); };

    // 0. weight prep
    {
        W8 ws;
        auto mk = [](const float* s, __half* d, int K, int N, int off, int il) {
            WSeg w; w.src = s; w.dst = d; w.K = K; w.N = N;
            w.tilesX = N/32; w.tileOff = off; w.ileave = il; return w;
        };
        int off = 0;
        ws.w[0] = mk(sa_in_w,  sa_in_wT,  CCH, 3*CCH, off, 0); off += (3*CCH/32)*(CCH/32);
        ws.w[1] = mk(sa_out_w, sa_out_wT, CCH, CCH,   off, 0); off += (CCH/32)*(CCH/32);
        ws.w[2] = mk(ca_q_w,   ca_q_wT,   CCH, CCH,   off, 0); off += (CCH/32)*(CCH/32);
        ws.w[3] = mk(ca_k_w,   ca_k_wT,   DCTX, CCH,  off, 0); off += (CCH/32)*(DCTX/32);
        ws.w[4] = mk(ca_v_w,   ca_v_wT,   DCTX, CCH,  off, 0); off += (CCH/32)*(DCTX/32);
        ws.w[5] = mk(ca_out_w, ca_out_wT, CCH, CCH,   off, 0); off += (CCH/32)*(CCH/32);
        ws.w[6] = mk(lin1_w,   lin1_wT,   CCH, 8*CCH, off, 1); off += (8*CCH/32)*(CCH/32);
        ws.w[7] = mk(lin2_w,   lin2_wT,   4*CCH, CCH, off, 0); off += (CCH/32)*(4*CCH/32);
        wtrans_all<<<off, tblk>>>(ws);
    }
    {
        int e0 = CCH*CCH/4, e1 = CCH*CCH/4, e2 = MC*DCTX/4, e3 = CCH;
        cvt_all<<<(e0+e1+e2+e3 + 255)/256, 256>>>(conv1_w, conv1_wh, e0,
                                                  co_w, co_wh, e1,
                                                  context, hctx, e2,
                                                  lin1_b, lin1bi, e3);
    }

    // 1. GroupNorm + transpose
    gn_stats<<<NB*GRP, 1024>>>(x);
    gn_apply<<<tgrid, tblk>>>(x, gn_s, gn_b);

    // 2. conv1 (64-row tiles, 2-stage, 3 CTA/SM)
    gemm_s<<<g64(CCH, M), 256, SMEM_FOR(64,2)>>>(hgn, CCH, conv1_wh, conv1_b, nullptr,
                                                 xseq, nullptr, CCH, M, CCH, CCH);

    // 3. self-attention
    layernorm<<<M, 160>>>(xseq, ln1_s, ln1_b, ht);
    gemm_h<3><<<g128(3*CCH, M), 256, SMEM_FOR(128,3)>>>(ht, CCH, sa_in_wT, nullptr, nullptr,
                                                        (float*)hvt, hqkv, 3*CCH, M, 3*CCH, CCH);
    flash_h<<<dim3(HW/128, NB*NH), 256>>>(hqkv, hvt, hattn);
    gemm_s<<<g64(CCH, M), 256, SMEM_FOR(64,2)>>>(hattn, CCH, sa_out_wT, sa_out_b, xseq,
                                                 xseq, nullptr, CCH, M, CCH, CCH);

    // 4. cross-attention: q-proj + kv-proj fused (64-row tiles)
    layernorm<<<M, 160>>>(xseq, ln2_s, ln2_b, ht);
    {
        int nq  = (CCH/128) * (M/64);                 // 640
        int nkv = (2*CCH/128) * ((MC + 63)/64);       // 100
        gemm_dual<<<nq + nkv, 256, SMEM_FOR(64,2)>>>(
            ht, CCH, ca_q_wT, hqkv, CCH, M, CCH, CCH, CCH/128, nq,
            hctx, DCTX, ca_k_wT, hkv, 2*CCH, MC, 2*CCH, DCTX, 2*CCH/128);
    }
    xattn_h<<<dim3(HW/128, NB*NH), 256>>>(hqkv, hkv, hattn);
    gemm_s<<<g64(CCH, M), 256, SMEM_FOR(64,2)>>>(hattn, CCH, ca_out_wT, ca_out_b, xseq,
                                                 xseq, nullptr, CCH, M, CCH, CCH);

    // 5. GeGLU FFN
    layernorm<<<M, 160>>>(xseq, ln3_s, ln3_b, ht);
    gemm_h<1><<<g128(8*CCH, M), 256, SMEM_FOR(128,3)>>>(ht, CCH, lin1_wT, lin1bi, nullptr,
                                                        nullptr, hffg, 4*CCH, M, 8*CCH, CCH);
    gemm_s<<<g64(CCH, M), 256, SMEM_FOR(64,2)>>>(hffg, 4*CCH, lin2_wT, lin2_b, xseq,
                                                 nullptr, hx, CCH, M, CCH, 4*CCH);

    // 6. final conv + long residual
    gemm_h<2><<<g128(CCH, M), 256, SMEM_FOR(128,3)>>>(hx, CCH, co_wh, co_b, x,
                                                      out, nullptr, CCH, M, CCH, CCH);
}